// round 13
// baseline (speedup 1.0000x reference)
#include <cuda_runtime.h>
#include <cstdint>

#define VSZ  10000   // vocab
#define KD   300     // embedding dim D
#define BB   256     // batch
#define TT   128     // max doc len
#define PP   200     // patterns

#define QP   704     // packed q columns (700 real, padded to 11*64)
#define KPAD 304     // K padded to 38*8
#define NKT  38      // k-tiles of 8
#define UPAD 10112   // 79 v-tiles of 128
#define VTM  79
#define JT   11      // j tiles of 64
#define NW   313     // bitmap words (10000 bits)
#define PACK_BLOCKS ((KPAD * QP) / 256)   // 836 (exact)

#define RING 10      // scan: warp-private ring slots
#define SD   8       // scan: prefetch distance (tokens)

// Device scratch (no allocation allowed)
__device__ __align__(16) float    g_table[(size_t)UPAD * QP];   // 28.5 MB [slot][j]
__device__ __align__(16) float    g_Bpack[(size_t)KPAD * QP];   // 0.86 MB [k][j]
__device__ float    g_biasp[QP];
__device__ uint32_t g_bits[NW + 7];   // zeroed at load & at end of slot_kernel
__device__ int      g_slot[VSZ];      // token -> compact slot
__device__ int      g_inv[UPAD];      // slot -> token (0-filled tail)
__device__ int      g_u;              // number of present tokens

__device__ __forceinline__ uint32_t smem_u32(const void* p) {
    uint32_t a;
    asm("{ .reg .u64 t; cvta.to.shared.u64 t, %1; cvt.u32.u64 %0, t; }" : "=r"(a) : "l"(p));
    return a;
}

// packed j (0..699) -> source q = p*5 + l   (end_states = repeat([2,3,4,5],50))
__device__ __forceinline__ int packed_to_src(int j) {
    if (j < 100) return (j >> 1) * 5 + (j & 1);
    if (j < 250) { int r = j - 100; return (50  + r / 3) * 5 + r % 3; }
    if (j < 450) { int r = j - 250; return (100 + r / 4) * 5 + r % 4; }
    { int r = j - 450; return (150 + r / 5) * 5 + r % 5; }
}

// pattern p (0..200) -> packed column base (700 at p=200)
__device__ __forceinline__ int base_of(int p) {
    return (p < 50)  ? 2 * p
         : (p < 100) ? 100 + 3 * (p - 50)
         : (p < 150) ? 250 + 4 * (p - 100)
         : (p < 200) ? 450 + 5 * (p - 150)
                     : 700;
}

// ---------------------------------------------------------------------------
// 1) fused prep: blocks [0, PACK_BLOCKS) pack B+bias; last BB blocks mark bits
// ---------------------------------------------------------------------------
__global__ void __launch_bounds__(256) prep_kernel(const float* __restrict__ diags,
                                                   const float* __restrict__ bias,
                                                   const int* __restrict__ docs,
                                                   const int* __restrict__ doc_lens) {
    const int bx = blockIdx.x, tid = threadIdx.x;
    if (bx < PACK_BLOCKS) {
        int idx = bx * 256 + tid;
        int k = idx / QP, j = idx % QP;
        g_Bpack[idx] = (k < KD && j < 700) ? diags[packed_to_src(j) * KD + k] : 0.f;
        if (idx < QP)
            g_biasp[idx] = (idx < 700) ? bias[packed_to_src(idx)] : 0.f;
    } else {
        int b = bx - PACK_BLOCKS;
        if (tid < TT && tid < doc_lens[b]) {
            int v = docs[b * TT + tid];
            atomicOr(&g_bits[v >> 5], 1u << (v & 31));
        }
    }
}

// ---------------------------------------------------------------------------
// 2) parallel prefix over bitmap -> slot/inv/u; zero bitmap for next call
// ---------------------------------------------------------------------------
__global__ void __launch_bounds__(512) slot_kernel() {
    __shared__ int pre[NW];
    __shared__ int wtot[16];
    __shared__ int s_u;
    const int tid = threadIdx.x, lane = tid & 31, w = tid >> 5;

    int val = (tid < NW) ? __popc(g_bits[tid]) : 0;
    int incl = val;
#pragma unroll
    for (int o = 1; o < 32; o <<= 1) {
        int y = __shfl_up_sync(0xffffffffu, incl, o);
        if (lane >= o) incl += y;
    }
    if (lane == 31) wtot[w] = incl;
    __syncthreads();
    if (w == 0) {
        int t = (lane < 16) ? wtot[lane] : 0;
#pragma unroll
        for (int o = 1; o < 16; o <<= 1) {
            int y = __shfl_up_sync(0xffffffffu, t, o);
            if (lane >= o) t += y;
        }
        if (lane < 16) wtot[lane] = t;
        if (lane == 15) s_u = t;
    }
    __syncthreads();
    int off = (w > 0) ? wtot[w - 1] : 0;
    if (tid < NW) pre[tid] = incl - val + off;
    if (tid == 0) g_u = s_u;
    __syncthreads();

    const int u = s_u;
    for (int v = tid; v < VSZ; v += 512) {
        uint32_t word = g_bits[v >> 5];
        int bit = v & 31;
        bool present = (word >> bit) & 1u;
        int s = pre[v >> 5] + __popc(word & ((1u << bit) - 1u));
        g_slot[v] = present ? s : -1;
        if (present) g_inv[s] = v;
    }
    for (int s = u + tid; s < UPAD; s += 512) g_inv[s] = 0;

    __syncthreads();
    if (tid < NW + 7) g_bits[tid] = 0u;
}

// ---------------------------------------------------------------------------
// 3) GEMM (unchanged from R11/R12 — measured at the FFMA-3reg roofline)
// ---------------------------------------------------------------------------
__global__ void __launch_bounds__(128, 4) gemm_kernel(const float* __restrict__ emb) {
    const int u = g_u;
    const int v0 = blockIdx.y * 128;
    if (v0 >= u) return;

    __shared__ __align__(16) float As[2][8][128];
    __shared__ __align__(16) float Bs[2][8][64];

    const int tid = threadIdx.x;
    const int ln  = tid & 15;
    const int ck  = tid >> 4;
    const int tv  = tid & 15;
    const int tq  = tid >> 4;
    const int j0  = blockIdx.x * 64;

    int iv[8];
#pragma unroll
    for (int s = 0; s < 8; s++) iv[s] = g_inv[v0 + ln + s * 16];

    const uint32_t sbB = smem_u32(Bs);
    auto issue_B = [&](int kt, int bf) {
        const float* gb = g_Bpack + (size_t)(kt * 8 + ck) * QP + j0 + ln * 4;
        uint32_t db = sbB + (bf * 2048 + ck * 256 + ln * 16);
        asm volatile("cp.async.cg.shared.global [%0], [%1], 16;" :: "r"(db), "l"(gb));
    };
    auto ldg_A = [&](int kt, float* av) {
        int gk = kt * 8 + ck;
        const float* rowp = emb + (size_t)gk * VSZ;
        bool ok = gk < KD;
#pragma unroll
        for (int s = 0; s < 8; s++) av[s] = ok ? __ldg(rowp + iv[s]) : 0.f;
    };
    auto sts_A = [&](int bf, const float* av) {
#pragma unroll
        for (int s = 0; s < 8; s++) As[bf][ck][ln + s * 16] = av[s];
    };

    float acc[8][8];
#pragma unroll
    for (int r = 0; r < 8; r++)
#pragma unroll
        for (int j = 0; j < 8; j++) acc[r][j] = 0.f;

    {
        float av[8];
        ldg_A(0, av);
        issue_B(0, 0);
        asm volatile("cp.async.commit_group;");
        sts_A(0, av);
        asm volatile("cp.async.wait_group 0;");
        __syncthreads();
    }

    for (int kt = 0; kt < NKT; kt++) {
        const bool more = (kt + 1 < NKT);
        float av[8];
        if (more) {
            ldg_A(kt + 1, av);
            issue_B(kt + 1, (kt + 1) & 1);
        }
        asm volatile("cp.async.commit_group;");

        const int c = kt & 1;
#pragma unroll
        for (int kk = 0; kk < 8; kk++) {
            const float4* ap = reinterpret_cast<const float4*>(&As[c][kk][tv * 8]);
            float4 a0 = ap[0], a1 = ap[1];
            const float4* bp = reinterpret_cast<const float4*>(&Bs[c][kk][tq * 8]);
            float4 b0 = bp[0], b1 = bp[1];
            float a[8] = {a0.x, a0.y, a0.z, a0.w, a1.x, a1.y, a1.z, a1.w};
            float b[8] = {b0.x, b0.y, b0.z, b0.w, b1.x, b1.y, b1.z, b1.w};
#pragma unroll
            for (int r = 0; r < 8; r++)
#pragma unroll
                for (int j = 0; j < 8; j++)
                    acc[r][j] += a[r] * b[j];
        }

        if (more) sts_A((kt + 1) & 1, av);
        asm volatile("cp.async.wait_group 0;");
        __syncthreads();
    }

    float bv[8];
#pragma unroll
    for (int j = 0; j < 8; j++) bv[j] = g_biasp[j0 + tq * 8 + j];

#pragma unroll
    for (int r = 0; r < 8; r++) {
        int i = v0 + tv * 8 + r;
        if (i < u) {
            float4* dst = reinterpret_cast<float4*>(&g_table[(size_t)i * QP + j0 + tq * 8]);
            dst[0] = make_float4(acc[r][0] + bv[0], acc[r][1] + bv[1],
                                 acc[r][2] + bv[2], acc[r][3] + bv[3]);
            dst[1] = make_float4(acc[r][4] + bv[4], acc[r][5] + bv[5],
                                 acc[r][6] + bv[6], acc[r][7] + bv[7]);
        }
    }
}

// ---------------------------------------------------------------------------
// 4) Scan: warp-private pipelines. Warp w owns patterns 25w..25w+24 and
//    fetches only its contiguous packed-column slice (<=128 floats) per token.
//    NO block barriers in the main loop — wait_group + __syncwarp only.
// ---------------------------------------------------------------------------
__global__ void __launch_bounds__(256) scan_kernel(const int* __restrict__ docs,
                                                   const int* __restrict__ doc_lens,
                                                   const int* __restrict__ end_states,
                                                   const float* __restrict__ wild,
                                                   const float* __restrict__ lin_w,
                                                   const float* __restrict__ lin_b,
                                                   float* __restrict__ out)
{
    __shared__ __align__(16) float ring[8][RING][128];   // 40 KB, warp-private rows
    __shared__ int   toks[TT];
    __shared__ float scs[PP];
    __shared__ float wsum[8];
    __shared__ float wsum2[2][8];
    __shared__ float s_mean;

    const int b    = blockIdx.x;
    const int tid  = threadIdx.x;
    const int w    = tid >> 5, lane = tid & 31;
    const int len  = doc_lens[b];

    if (tid < TT) toks[tid] = g_slot[docs[b * TT + tid]];   // valid for t < len

    // warp slice geometry (uniform within warp)
    const int astart = base_of(w * 25) & ~3;
    const int slen   = base_of(w * 25 + 25) - astart;       // <= 128
    const bool fet   = (lane * 4) < slen;                   // this lane fetches 16B

    const bool act = lane < 25;                             // pattern p = 25w + lane
    const int  p   = w * 25 + lane;
    float w0 = 0.f, w1 = 0.f, w2 = 0.f, w3 = 0.f, w4 = 0.f;
    int e = 2, off = 0;
    if (act) {
        w0 = wild[p * 5 + 0];
        w1 = wild[p * 5 + 1];
        w2 = wild[p * 5 + 2];
        w3 = wild[p * 5 + 3];
        w4 = wild[p * 5 + 4];
        e  = end_states[p];
        off = base_of(p) - astart;
    }
    __syncthreads();                                        // toks visible

    const float NEG = __int_as_float(0xff800000);
    float h1 = NEG, h2 = NEG, h3 = NEG, h4 = NEG, h5 = NEG, sc = NEG;

    const uint32_t sbase = smem_u32(ring) + w * (RING * 512);
    auto fetch_row = [&](int t, int slot) {                 // caller guards t < len
        if (fet) {
            const float* g = g_table + (size_t)toks[t] * QP + astart + lane * 4;
            uint32_t dd = sbase + slot * 512 + lane * 16;
            asm volatile("cp.async.cg.shared.global [%0], [%1], 16;" :: "r"(dd), "l"(g));
        }
    };
    auto step = [&](int slot) {
        const float* r = &ring[w][slot][off];
        float t0 = r[0];
        float t1 = r[1];
        float t2 = (e > 2) ? r[2] : NEG;
        float t3 = (e > 3) ? r[3] : NEG;
        float t4 = (e > 4) ? r[4] : NEG;
        float m0 = fmaxf(t0, w0);
        float m1 = fmaxf(t1, w1);
        float m2 = fmaxf(t2, w2);
        float m3 = fmaxf(t3, w3);
        float m4 = fmaxf(t4, w4);
        h5 = h4 + m4;          // uses OLD h4..h1
        h4 = h3 + m3;
        h3 = h2 + m2;
        h2 = h1 + m1;
        h1 = m0;
        float ev = (e == 2) ? h2 : (e == 3) ? h3 : (e == 4) ? h4 : h5;
        sc = fmaxf(sc, ev);
    };

    // prologue: tokens 0..SD-1 (len >= 8 == SD always)
#pragma unroll
    for (int t = 0; t < SD; t++) {
        fetch_row(t, t);
        asm volatile("cp.async.commit_group;");
    }

    int cslot = 0, fslot = SD % RING;
    for (int t = 0; t < len; t++) {
        int ft = t + SD;
        if (ft < len) fetch_row(ft, fslot);
        asm volatile("cp.async.commit_group;");
        asm volatile("cp.async.wait_group %0;" :: "n"(SD));
        __syncwarp();
        if (act) step(cslot);
        if (++cslot == RING) cslot = 0;
        if (++fslot == RING) fslot = 0;
    }

    // stage scores so the reduction below keeps the ORIGINAL p=tid order
    if (act) scs[p] = sc;
    __syncthreads();

    const int rwarp = tid >> 5, rlane = tid & 31;
    float x = (tid < PP) ? scs[tid] : 0.f;
#pragma unroll
    for (int o = 16; o; o >>= 1) x += __shfl_down_sync(0xffffffffu, x, o);
    if (rlane == 0) wsum[rwarp] = x;
    __syncthreads();
    if (tid == 0) {
        float tot = 0.f;
#pragma unroll
        for (int i = 0; i < 8; i++) tot += wsum[i];
        s_mean = tot / 200.f;
    }
    __syncthreads();
    const float mean = s_mean;

    float c0 = 0.f, c1 = 0.f;
    if (tid < PP && scs[tid] > mean) {
        c0 = lin_w[tid];
        c1 = lin_w[PP + tid];
    }
#pragma unroll
    for (int o = 16; o; o >>= 1) {
        c0 += __shfl_down_sync(0xffffffffu, c0, o);
        c1 += __shfl_down_sync(0xffffffffu, c1, o);
    }
    if (rlane == 0) { wsum2[0][rwarp] = c0; wsum2[1][rwarp] = c1; }
    __syncthreads();
    if (tid == 0) {
        float t0 = 0.f, t1 = 0.f;
#pragma unroll
        for (int i = 0; i < 8; i++) { t0 += wsum2[0][i]; t1 += wsum2[1][i]; }
        out[b * 2 + 0] = t0 + lin_b[0];
        out[b * 2 + 1] = t1 + lin_b[1];
    }
}

// ---------------------------------------------------------------------------
extern "C" void kernel_launch(void* const* d_in, const int* in_sizes, int n_in,
                              void* d_out, int out_size)
{
    const int*   docs       = (const int*)  d_in[0];
    const int*   doc_lens   = (const int*)  d_in[1];
    const int*   end_states = (const int*)  d_in[2];
    const float* emb        = (const float*)d_in[3];
    const float* diags      = (const float*)d_in[4];
    const float* bias       = (const float*)d_in[5];
    const float* wild       = (const float*)d_in[6];
    const float* lin_w      = (const float*)d_in[7];
    const float* lin_b      = (const float*)d_in[8];
    float* out = (float*)d_out;

    prep_kernel<<<PACK_BLOCKS + BB, 256>>>(diags, bias, docs, doc_lens);
    slot_kernel<<<1, 512>>>();
    gemm_kernel<<<dim3(JT, VTM), 128>>>(emb);
    scan_kernel<<<BB, 256>>>(docs, doc_lens, end_states, wild, lin_w, lin_b, out);
}

// round 16
// speedup vs baseline: 1.0136x; 1.0136x over previous
#include <cuda_runtime.h>
#include <cstdint>

#define VSZ  10000   // vocab
#define KD   300     // embedding dim D
#define BB   256     // batch
#define TT   128     // max doc len
#define PP   200     // patterns

#define QP   704     // packed q columns (700 real, padded to 11*64)
#define KPAD 304     // K padded to 38*8
#define NKT  38      // k-tiles of 8
#define UPAD 10112   // 79 v-tiles of 128
#define VTM  79
#define JT   11      // j tiles of 64
#define NW   313     // bitmap words (10000 bits)
#define PACK_BLOCKS ((KPAD * QP) / 256)   // 836 (exact)

#define RING 10      // scan: warp-private ring slots
#define SD   8       // scan: prefetch distance (tokens)

// Device scratch (no allocation allowed)
__device__ __align__(128) float   g_table[(size_t)UPAD * QP];   // 28.5 MB [slot][j]
__device__ __align__(16)  float   g_Bpack[(size_t)KPAD * QP];   // 0.86 MB [k][j]
__device__ float    g_biasp[QP];
__device__ uint32_t g_bits[NW + 7];   // zeroed at load & at end of slot_kernel
__device__ int      g_slot[VSZ];      // token -> compact slot
__device__ int      g_inv[UPAD];      // slot -> token (0-filled tail)
__device__ int      g_u;              // number of present tokens

__device__ __forceinline__ uint32_t smem_u32(const void* p) {
    uint32_t a;
    asm("{ .reg .u64 t; cvta.to.shared.u64 t, %1; cvt.u32.u64 %0, t; }" : "=r"(a) : "l"(p));
    return a;
}

// persistent store: 32B (v8.b32) with L2 evict-last — keeps table in L2 for scan
__device__ __forceinline__ void stg_persist8(float* p, const float* v) {
    asm volatile("st.global.L2::evict_last.v8.b32 [%0], {%1,%2,%3,%4,%5,%6,%7,%8};"
                 :: "l"(p),
                    "r"(__float_as_uint(v[0])), "r"(__float_as_uint(v[1])),
                    "r"(__float_as_uint(v[2])), "r"(__float_as_uint(v[3])),
                    "r"(__float_as_uint(v[4])), "r"(__float_as_uint(v[5])),
                    "r"(__float_as_uint(v[6])), "r"(__float_as_uint(v[7]))
                 : "memory");
}

// packed j (0..699) -> source q = p*5 + l   (end_states = repeat([2,3,4,5],50))
__device__ __forceinline__ int packed_to_src(int j) {
    if (j < 100) return (j >> 1) * 5 + (j & 1);
    if (j < 250) { int r = j - 100; return (50  + r / 3) * 5 + r % 3; }
    if (j < 450) { int r = j - 250; return (100 + r / 4) * 5 + r % 4; }
    { int r = j - 450; return (150 + r / 5) * 5 + r % 5; }
}

// pattern p (0..200) -> packed column base (700 at p=200)
__device__ __forceinline__ int base_of(int p) {
    return (p < 50)  ? 2 * p
         : (p < 100) ? 100 + 3 * (p - 50)
         : (p < 150) ? 250 + 4 * (p - 100)
         : (p < 200) ? 450 + 5 * (p - 150)
                     : 700;
}

// ---------------------------------------------------------------------------
// 1) fused prep: blocks [0, PACK_BLOCKS) pack B+bias; last BB blocks mark bits
// ---------------------------------------------------------------------------
__global__ void __launch_bounds__(256) prep_kernel(const float* __restrict__ diags,
                                                   const float* __restrict__ bias,
                                                   const int* __restrict__ docs,
                                                   const int* __restrict__ doc_lens) {
    const int bx = blockIdx.x, tid = threadIdx.x;
    if (bx < PACK_BLOCKS) {
        int idx = bx * 256 + tid;
        int k = idx / QP, j = idx % QP;
        g_Bpack[idx] = (k < KD && j < 700) ? diags[packed_to_src(j) * KD + k] : 0.f;
        if (idx < QP)
            g_biasp[idx] = (idx < 700) ? bias[packed_to_src(idx)] : 0.f;
    } else {
        int b = bx - PACK_BLOCKS;
        if (tid < TT && tid < doc_lens[b]) {
            int v = docs[b * TT + tid];
            atomicOr(&g_bits[v >> 5], 1u << (v & 31));
        }
    }
}

// ---------------------------------------------------------------------------
// 2) parallel prefix over bitmap -> slot/inv/u; zero bitmap for next call
// ---------------------------------------------------------------------------
__global__ void __launch_bounds__(512) slot_kernel() {
    __shared__ int pre[NW];
    __shared__ int wtot[16];
    __shared__ int s_u;
    const int tid = threadIdx.x, lane = tid & 31, w = tid >> 5;

    int val = (tid < NW) ? __popc(g_bits[tid]) : 0;
    int incl = val;
#pragma unroll
    for (int o = 1; o < 32; o <<= 1) {
        int y = __shfl_up_sync(0xffffffffu, incl, o);
        if (lane >= o) incl += y;
    }
    if (lane == 31) wtot[w] = incl;
    __syncthreads();
    if (w == 0) {
        int t = (lane < 16) ? wtot[lane] : 0;
#pragma unroll
        for (int o = 1; o < 16; o <<= 1) {
            int y = __shfl_up_sync(0xffffffffu, t, o);
            if (lane >= o) t += y;
        }
        if (lane < 16) wtot[lane] = t;
        if (lane == 15) s_u = t;
    }
    __syncthreads();
    int off = (w > 0) ? wtot[w - 1] : 0;
    if (tid < NW) pre[tid] = incl - val + off;
    if (tid == 0) g_u = s_u;
    __syncthreads();

    const int u = s_u;
    for (int v = tid; v < VSZ; v += 512) {
        uint32_t word = g_bits[v >> 5];
        int bit = v & 31;
        bool present = (word >> bit) & 1u;
        int s = pre[v >> 5] + __popc(word & ((1u << bit) - 1u));
        g_slot[v] = present ? s : -1;
        if (present) g_inv[s] = v;
    }
    for (int s = u + tid; s < UPAD; s += 512) g_inv[s] = 0;

    __syncthreads();
    if (tid < NW + 7) g_bits[tid] = 0u;
}

// ---------------------------------------------------------------------------
// 3) GEMM (FFMA-roofline loop unchanged; table stores evict_last v8 so the
//    28.5 MB table stays L2-resident for the scan)
// ---------------------------------------------------------------------------
__global__ void __launch_bounds__(128, 4) gemm_kernel(const float* __restrict__ emb) {
    const int u = g_u;
    const int v0 = blockIdx.y * 128;
    if (v0 >= u) return;

    __shared__ __align__(16) float As[2][8][128];
    __shared__ __align__(16) float Bs[2][8][64];

    const int tid = threadIdx.x;
    const int ln  = tid & 15;
    const int ck  = tid >> 4;
    const int tv  = tid & 15;
    const int tq  = tid >> 4;
    const int j0  = blockIdx.x * 64;

    int iv[8];
#pragma unroll
    for (int s = 0; s < 8; s++) iv[s] = g_inv[v0 + ln + s * 16];

    const uint32_t sbB = smem_u32(Bs);
    auto issue_B = [&](int kt, int bf) {
        const float* gb = g_Bpack + (size_t)(kt * 8 + ck) * QP + j0 + ln * 4;
        uint32_t db = sbB + (bf * 2048 + ck * 256 + ln * 16);
        asm volatile("cp.async.cg.shared.global [%0], [%1], 16;" :: "r"(db), "l"(gb));
    };
    auto ldg_A = [&](int kt, float* av) {
        int gk = kt * 8 + ck;
        const float* rowp = emb + (size_t)gk * VSZ;
        bool ok = gk < KD;
#pragma unroll
        for (int s = 0; s < 8; s++) av[s] = ok ? __ldg(rowp + iv[s]) : 0.f;
    };
    auto sts_A = [&](int bf, const float* av) {
#pragma unroll
        for (int s = 0; s < 8; s++) As[bf][ck][ln + s * 16] = av[s];
    };

    float acc[8][8];
#pragma unroll
    for (int r = 0; r < 8; r++)
#pragma unroll
        for (int j = 0; j < 8; j++) acc[r][j] = 0.f;

    {
        float av[8];
        ldg_A(0, av);
        issue_B(0, 0);
        asm volatile("cp.async.commit_group;");
        sts_A(0, av);
        asm volatile("cp.async.wait_group 0;");
        __syncthreads();
    }

    for (int kt = 0; kt < NKT; kt++) {
        const bool more = (kt + 1 < NKT);
        float av[8];
        if (more) {
            ldg_A(kt + 1, av);
            issue_B(kt + 1, (kt + 1) & 1);
        }
        asm volatile("cp.async.commit_group;");

        const int c = kt & 1;
#pragma unroll
        for (int kk = 0; kk < 8; kk++) {
            const float4* ap = reinterpret_cast<const float4*>(&As[c][kk][tv * 8]);
            float4 a0 = ap[0], a1 = ap[1];
            const float4* bp = reinterpret_cast<const float4*>(&Bs[c][kk][tq * 8]);
            float4 b0 = bp[0], b1 = bp[1];
            float a[8] = {a0.x, a0.y, a0.z, a0.w, a1.x, a1.y, a1.z, a1.w};
            float b[8] = {b0.x, b0.y, b0.z, b0.w, b1.x, b1.y, b1.z, b1.w};
#pragma unroll
            for (int r = 0; r < 8; r++)
#pragma unroll
                for (int j = 0; j < 8; j++)
                    acc[r][j] += a[r] * b[j];
        }

        if (more) sts_A((kt + 1) & 1, av);
        asm volatile("cp.async.wait_group 0;");
        __syncthreads();
    }

    float bv[8];
#pragma unroll
    for (int j = 0; j < 8; j++) bv[j] = g_biasp[j0 + tq * 8 + j];

#pragma unroll
    for (int r = 0; r < 8; r++) {
        int i = v0 + tv * 8 + r;
        if (i < u) {
            float vals[8];
#pragma unroll
            for (int j = 0; j < 8; j++) vals[j] = acc[r][j] + bv[j];
            stg_persist8(&g_table[(size_t)i * QP + j0 + tq * 8], vals);
        }
    }
}

// ---------------------------------------------------------------------------
// 4) Scan: warp-private pipelines (R13 structure, against L2-resident table)
// ---------------------------------------------------------------------------
__global__ void __launch_bounds__(256) scan_kernel(const int* __restrict__ docs,
                                                   const int* __restrict__ doc_lens,
                                                   const int* __restrict__ end_states,
                                                   const float* __restrict__ wild,
                                                   const float* __restrict__ lin_w,
                                                   const float* __restrict__ lin_b,
                                                   float* __restrict__ out)
{
    __shared__ __align__(16) float ring[8][RING][128];   // 40 KB, warp-private rows
    __shared__ int   toks[TT];
    __shared__ float scs[PP];
    __shared__ float wsum[8];
    __shared__ float wsum2[2][8];
    __shared__ float s_mean;

    const int b    = blockIdx.x;
    const int tid  = threadIdx.x;
    const int w    = tid >> 5, lane = tid & 31;
    const int len  = doc_lens[b];

    if (tid < TT) toks[tid] = g_slot[docs[b * TT + tid]];   // valid for t < len

    const int astart = base_of(w * 25) & ~3;
    const int slen   = base_of(w * 25 + 25) - astart;       // <= 128
    const bool fet   = (lane * 4) < slen;

    const bool act = lane < 25;                             // pattern p = 25w + lane
    const int  p   = w * 25 + lane;
    float w0 = 0.f, w1 = 0.f, w2 = 0.f, w3 = 0.f, w4 = 0.f;
    int e = 2, off = 0;
    if (act) {
        w0 = wild[p * 5 + 0];
        w1 = wild[p * 5 + 1];
        w2 = wild[p * 5 + 2];
        w3 = wild[p * 5 + 3];
        w4 = wild[p * 5 + 4];
        e  = end_states[p];
        off = base_of(p) - astart;
    }
    __syncthreads();                                        // toks visible

    const float NEG = __int_as_float(0xff800000);
    float h1 = NEG, h2 = NEG, h3 = NEG, h4 = NEG, h5 = NEG, sc = NEG;

    const uint32_t sbase = smem_u32(ring) + w * (RING * 512);
    auto fetch_row = [&](int t, int slot) {
        if (fet) {
            const float* g = g_table + (size_t)toks[t] * QP + astart + lane * 4;
            uint32_t dd = sbase + slot * 512 + lane * 16;
            asm volatile("cp.async.cg.shared.global [%0], [%1], 16;" :: "r"(dd), "l"(g));
        }
    };
    auto step = [&](int slot) {
        const float* r = &ring[w][slot][off];
        float t0 = r[0];
        float t1 = r[1];
        float t2 = (e > 2) ? r[2] : NEG;
        float t3 = (e > 3) ? r[3] : NEG;
        float t4 = (e > 4) ? r[4] : NEG;
        float m0 = fmaxf(t0, w0);
        float m1 = fmaxf(t1, w1);
        float m2 = fmaxf(t2, w2);
        float m3 = fmaxf(t3, w3);
        float m4 = fmaxf(t4, w4);
        h5 = h4 + m4;          // uses OLD h4..h1
        h4 = h3 + m3;
        h3 = h2 + m2;
        h2 = h1 + m1;
        h1 = m0;
        float ev = (e == 2) ? h2 : (e == 3) ? h3 : (e == 4) ? h4 : h5;
        sc = fmaxf(sc, ev);
    };

#pragma unroll
    for (int t = 0; t < SD; t++) {                  // len >= 8 == SD always
        fetch_row(t, t);
        asm volatile("cp.async.commit_group;");
    }

    int cslot = 0, fslot = SD % RING;
    for (int t = 0; t < len; t++) {
        int ft = t + SD;
        if (ft < len) fetch_row(ft, fslot);
        asm volatile("cp.async.commit_group;");
        asm volatile("cp.async.wait_group %0;" :: "n"(SD));
        __syncwarp();
        if (act) step(cslot);
        if (++cslot == RING) cslot = 0;
        if (++fslot == RING) fslot = 0;
    }

    // stage scores so the reduction keeps the ORIGINAL p=tid order
    if (act) scs[p] = sc;
    __syncthreads();

    const int rwarp = tid >> 5, rlane = tid & 31;
    float x = (tid < PP) ? scs[tid] : 0.f;
#pragma unroll
    for (int o = 16; o; o >>= 1) x += __shfl_down_sync(0xffffffffu, x, o);
    if (rlane == 0) wsum[rwarp] = x;
    __syncthreads();
    if (tid == 0) {
        float tot = 0.f;
#pragma unroll
        for (int i = 0; i < 8; i++) tot += wsum[i];
        s_mean = tot / 200.f;
    }
    __syncthreads();
    const float mean = s_mean;

    float c0 = 0.f, c1 = 0.f;
    if (tid < PP && scs[tid] > mean) {
        c0 = lin_w[tid];
        c1 = lin_w[PP + tid];
    }
#pragma unroll
    for (int o = 16; o; o >>= 1) {
        c0 += __shfl_down_sync(0xffffffffu, c0, o);
        c1 += __shfl_down_sync(0xffffffffu, c1, o);
    }
    if (rlane == 0) { wsum2[0][rwarp] = c0; wsum2[1][rwarp] = c1; }
    __syncthreads();
    if (tid == 0) {
        float t0 = 0.f, t1 = 0.f;
#pragma unroll
        for (int i = 0; i < 8; i++) { t0 += wsum2[0][i]; t1 += wsum2[1][i]; }
        out[b * 2 + 0] = t0 + lin_b[0];
        out[b * 2 + 1] = t1 + lin_b[1];
    }
}

// ---------------------------------------------------------------------------
extern "C" void kernel_launch(void* const* d_in, const int* in_sizes, int n_in,
                              void* d_out, int out_size)
{
    const int*   docs       = (const int*)  d_in[0];
    const int*   doc_lens   = (const int*)  d_in[1];
    const int*   end_states = (const int*)  d_in[2];
    const float* emb        = (const float*)d_in[3];
    const float* diags      = (const float*)d_in[4];
    const float* bias       = (const float*)d_in[5];
    const float* wild       = (const float*)d_in[6];
    const float* lin_w      = (const float*)d_in[7];
    const float* lin_b      = (const float*)d_in[8];
    float* out = (float*)d_out;

    prep_kernel<<<PACK_BLOCKS + BB, 256>>>(diags, bias, docs, doc_lens);
    slot_kernel<<<1, 512>>>();
    gemm_kernel<<<dim3(JT, VTM), 128>>>(emb);
    scan_kernel<<<BB, 256>>>(docs, doc_lens, end_states, wild, lin_w, lin_b, out);
}